// round 5
// baseline (speedup 1.0000x reference)
#include <cuda_runtime.h>
#include <cstdint>

// Conv2d 3x3 s1 p1 via mma.sync tf32 implicit GEMM (compute_103-safe path).
// C[oc][px] = Wt[k][oc]^T * im2col(x), k tap-major (k = rs*128 + c).
// A (weights): tf32 prepass -> cp.async 3-stage smem pipeline.
// B (pixels):  gmem -> registers directly (__ldg + cvt.rna + edge masks),
//              prefetched one full k-tile ahead. No B smem, no x prepass.

#define HW    3136
#define CIN   128
#define COUT  256
#define KTOT  1152
#define NKT   72
#define LDA   136
#define ATILEF (16*LDA)
#define NSTAGE 3

__device__ float g_wt[KTOT * COUT];   // [k][oc], tf32-rounded

__global__ void wt_kernel(const float* __restrict__ W) {
    const int k = blockIdx.x;            // k = rs*128 + c
    const int oc = threadIdx.x;
    const int rs = k >> 7, c = k & 127;
    float v = W[oc * KTOT + c * 9 + rs];
    uint32_t t; asm("cvt.rna.tf32.f32 %0, %1;" : "=r"(t) : "f"(v));
    g_wt[k * COUT + oc] = __uint_as_float(t);
}

__device__ __forceinline__ void cp16(uint32_t d, const void* s) {
    asm volatile("cp.async.cg.shared.global [%0], [%1], 16;" :: "r"(d), "l"(s));
}
#define CP_COMMIT asm volatile("cp.async.commit_group;" ::: "memory")
#define CP_WAIT1  asm volatile("cp.async.wait_group 1;" ::: "memory")

__global__ void __launch_bounds__(128, 2)
conv_mma(const float* __restrict__ x,
         const float* __restrict__ bias,
         float* __restrict__ out)
{
    __shared__ float sm[NSTAGE * ATILEF];
    const uint32_t smb = (uint32_t)__cvta_generic_to_shared(sm);
    const int tid  = threadIdx.x;
    const int lane = tid & 31;
    const int wid  = tid >> 5;
    const int r    = lane >> 2, cq = lane & 3;
    const int p0   = blockIdx.x * 128;
    const int ni   = blockIdx.y;
    const int m0   = blockIdx.z * 128;
    const int wm0  = (wid & 1) * 64;
    const int wn0  = (wid >> 1) * 64;
    const float* xb = x + (size_t)ni * (CIN * HW);

    // per-thread pixels (one per nf) + edge flags
    int   pxo[8];
    uint32_t ef[8];   // bit0: oh==0, bit1: oh==55, bit2: ow==0, bit3: ow==55
#pragma unroll
    for (int nf = 0; nf < 8; nf++) {
        const int px = p0 + wn0 + nf * 8 + r;
        pxo[nf] = px;
        const int pc = px < HW ? px : HW - 1;
        const int oh = pc / 56, ow = pc - oh * 56;
        ef[nf] = (oh == 0) | ((oh == 55) << 1) | ((ow == 0) << 2) | ((ow == 55) << 3);
    }

    float acc[4][8][4];
#pragma unroll
    for (int mf = 0; mf < 4; mf++)
#pragma unroll
        for (int nf = 0; nf < 8; nf++)
#pragma unroll
            for (int e = 0; e < 4; e++) acc[mf][nf][e] = 0.0f;

    // ---- A tile cp.async issue ----
    auto issueA = [&](int kt) {
        const uint32_t As = smb + (kt % NSTAGE) * (ATILEF * 4);
#pragma unroll
        for (int q = 0; q < 4; q++) {
            const int idx = tid + q * 128;
            const int row = idx >> 5, col = (idx & 31) * 4;
            cp16(As + (row * LDA + col) * 4,
                 g_wt + (size_t)(kt * 16 + row) * COUT + m0 + col);
        }
    };

    // ---- B fragment load: gmem -> regs, cvt.rna + edge mask ----
    // b[ks][nf][h] = x[c0 + ks*8 + cq + h*4][px + shift], zeroed if tap off-image
    auto loadB = [&](int kt, uint32_t b[2][8][2]) {
        const int rs = kt >> 3;
        const int rr = rs / 3, sc = rs - rr * 3;
        const int shift = (rr - 1) * 56 + (sc - 1);
        const int c0 = (kt & 7) * 16;
        const uint32_t badmask = (rr == 0 ? 1u : 0u) | (rr == 2 ? 2u : 0u) |
                                 (sc == 0 ? 4u : 0u) | (sc == 2 ? 8u : 0u);
        const float* xc = xb + (size_t)(c0 + cq) * HW;
#pragma unroll
        for (int nf = 0; nf < 8; nf++) {
            int off = pxo[nf] + shift;
            off = off < 0 ? 0 : (off >= HW ? HW - 1 : off);   // safe addr; masked anyway
            const bool bad = (ef[nf] & badmask) != 0u;
            const float* bp = xc + off;
#pragma unroll
            for (int ks = 0; ks < 2; ks++)
#pragma unroll
                for (int h = 0; h < 2; h++) {
                    float f = __ldg(bp + (size_t)(ks * 8 + h * 4) * HW);
                    f = bad ? 0.0f : f;
                    asm("cvt.rna.tf32.f32 %0, %1;" : "=r"(b[ks][nf][h]) : "f"(f));
                }
        }
    };

    issueA(0); CP_COMMIT;
    issueA(1); CP_COMMIT;

    uint32_t bcur[2][8][2], bnxt[2][8][2];
    loadB(0, bcur);

#pragma unroll 1
    for (int kt = 0; kt < NKT; kt++) {
        CP_WAIT1;
        __syncthreads();

        if (kt + 2 < NKT) issueA(kt + 2);
        CP_COMMIT;
        if (kt + 1 < NKT) loadB(kt + 1, bnxt);

        const float* Asf = sm + (kt % NSTAGE) * ATILEF;
#pragma unroll
        for (int ks = 0; ks < 2; ks++) {
            uint32_t a[4][4];
            const float* ap = Asf + (ks * 8 + cq) * LDA + wm0 + r;
#pragma unroll
            for (int mf = 0; mf < 4; mf++) {
                a[mf][0] = __float_as_uint(ap[mf * 16]);
                a[mf][1] = __float_as_uint(ap[mf * 16 + 8]);
                a[mf][2] = __float_as_uint(ap[4 * LDA + mf * 16]);
                a[mf][3] = __float_as_uint(ap[4 * LDA + mf * 16 + 8]);
            }
#pragma unroll
            for (int mf = 0; mf < 4; mf++)
#pragma unroll
                for (int nf = 0; nf < 8; nf++)
                    asm volatile(
                        "mma.sync.aligned.m16n8k8.row.col.f32.tf32.tf32.f32 "
                        "{%0,%1,%2,%3}, {%4,%5,%6,%7}, {%8,%9}, {%0,%1,%2,%3};"
                        : "+f"(acc[mf][nf][0]), "+f"(acc[mf][nf][1]),
                          "+f"(acc[mf][nf][2]), "+f"(acc[mf][nf][3])
                        : "r"(a[mf][0]), "r"(a[mf][1]), "r"(a[mf][2]), "r"(a[mf][3]),
                          "r"(bcur[ks][nf][0]), "r"(bcur[ks][nf][1]));
        }

#pragma unroll
        for (int ks = 0; ks < 2; ks++)
#pragma unroll
            for (int nf = 0; nf < 8; nf++) {
                bcur[ks][nf][0] = bnxt[ks][nf][0];
                bcur[ks][nf][1] = bnxt[ks][nf][1];
            }
    }

    // ---- epilogue ----
    const size_t obase = (size_t)ni * COUT * HW;
#pragma unroll
    for (int mf = 0; mf < 4; mf++) {
        const int mg = m0 + wm0 + mf * 16 + r;
        const float b0 = __ldg(bias + mg);
        const float b1 = __ldg(bias + mg + 8);
        float* o0 = out + obase + (size_t)mg * HW;
#pragma unroll
        for (int nf = 0; nf < 8; nf++) {
            const int px = p0 + wn0 + nf * 8 + cq * 2;
            if (px < HW) {
                float2 v0 = make_float2(acc[mf][nf][0] + b0, acc[mf][nf][1] + b0);
                float2 v1 = make_float2(acc[mf][nf][2] + b1, acc[mf][nf][3] + b1);
                *reinterpret_cast<float2*>(o0 + px) = v0;
                *reinterpret_cast<float2*>(o0 + (size_t)8 * HW + px) = v1;
            }
        }
    }
}

extern "C" void kernel_launch(void* const* d_in, const int* in_sizes, int n_in,
                              void* d_out, int out_size)
{
    const float* x    = (const float*)d_in[0];
    const float* W    = (const float*)d_in[1];
    const float* bias = (const float*)d_in[2];
    float* out        = (float*)d_out;

    wt_kernel<<<KTOT, COUT>>>(W);
    dim3 grid(25, 32, 2);
    conv_mma<<<grid, 128>>>(x, bias, out);
}